// round 11
// baseline (speedup 1.0000x reference)
#include <cuda_runtime.h>
#include <math.h>
#include <stdint.h>

#define NVERT 300000
#define NPOS  500000

// ---------------- device scratch (no allocs allowed) ----------------
__device__ float  g_x1[NVERT * 64];
__device__ float  g_x2[NVERT * 32];
__device__ float  g_x3[NVERT * 8];
__device__ float  g_proj[NVERT * 20];
__device__ double g_acc[320];          // lv @0, x1 @128, x2 @256 (sum|sumsq)
__device__ float  g_scale[160];
__device__ float  g_shift[160];

__global__ void init_acc_kernel() {
    int i = threadIdx.x;
    if (i < 320) g_acc[i] = 0.0;
}

// ---------------- stats -> per-channel affine (GN folded) ----------------
template <int C>
__global__ void finalize_kernel(const double* __restrict__ acc,
                                const float* __restrict__ w, const float* __restrict__ b,
                                float* __restrict__ scale, float* __restrict__ shift, int nrows) {
    int c = threadIdx.x;
    if (c >= C) return;
    constexpr int CPG = C / 32;
    int g = c / CPG;
    double s = 0.0, q = 0.0;
#pragma unroll
    for (int j = 0; j < CPG; j++) {
        s += acc[g * CPG + j];
        q += acc[C + g * CPG + j];
    }
    double n   = (double)nrows * (double)CPG;
    double mu  = s / n;
    double var = q / n - mu * mu;
    float  rs  = (float)(1.0 / sqrt(var + 1e-5));
    float  sc  = w[c] * rs;
    scale[c] = sc;
    shift[c] = b[c] - (float)mu * sc;
}

// ---------------- tf32 mma helpers (legacy mma.sync, sm_80+ PTX) ----------------
__device__ __forceinline__ uint32_t f2tf32(float x) {
    uint32_t r;
    asm("cvt.rna.tf32.f32 %0, %1;" : "=r"(r) : "f"(x));
    return r;
}
__device__ __forceinline__ void mma8(float* c, const uint32_t* a, uint32_t b0, uint32_t b1) {
    asm volatile("mma.sync.aligned.m16n8k8.row.col.f32.tf32.tf32.f32 "
                 "{%0,%1,%2,%3}, {%4,%5,%6,%7}, {%8,%9}, {%0,%1,%2,%3};"
                 : "+f"(c[0]), "+f"(c[1]), "+f"(c[2]), "+f"(c[3])
                 : "r"(a[0]), "r"(a[1]), "r"(a[2]), "r"(a[3]), "r"(b0), "r"(b1));
}

// =====================================================================
// tf32 tensor-core GEMM: Y[r,o] = sum_k f(X[r,k]) * W[o,k], M=128/CTA.
// f = relu(x*scale+shift) if AFF. 3-term split-tf32 (fp32-accurate):
// D = ah*bh + ah*bl + al*bh.
// W is pre-converted to (hi,lo) tf32 in mma-fragment layout at staging:
// 16B cell per (n,kb,g,t) = [bh0, bh1, bl0, bl1] -> single LDS.128 in loop.
// INSTATS: channel stats of raw X fused into staging.
// OUTSTATS: channel stats of Y fused via fragment shfl-reduce.
// =====================================================================
template <int CIN, int NOUT, int NPAD, bool AFF, bool INSTATS, bool OUTSTATS>
__global__ void __launch_bounds__(256)
mgemm_kernel(const float* __restrict__ X, const float* __restrict__ W,
             const float* __restrict__ scale, const float* __restrict__ shift,
             float* __restrict__ Y, double* __restrict__ accout, int nrows) {
    constexpr int M = 128, LDA = CIN + 4, NT = NPAD / 8, KS = CIN / 8;
    extern __shared__ float sm[];
    float*    sA = sm;                            // [M][LDA] raw (affine+relu applied)
    uint32_t* sB = (uint32_t*)(sA + M * LDA);     // NPAD*CIN*2 u32, fragment layout
    float*    sS = (float*)(sB + NPAD * CIN * 2); // [256]

    int tid = threadIdx.x, lane = tid & 31, wid = tid >> 5;
    int g = lane >> 2, t = lane & 3;
    int row0 = blockIdx.x * M;

    if (INSTATS || OUTSTATS) sS[tid] = 0.f;

    // ---- stage W: convert once to (hi,lo) tf32, fragment layout ----
    for (int i = tid; i < NPAD * CIN; i += 256) {
        int o = i / CIN, c = i % CIN;
        float w = (o < NOUT) ? W[o * CIN + c] : 0.f;
        uint32_t hi = f2tf32(w);
        uint32_t lo = f2tf32(w - __uint_as_float(hi));
        int n = o >> 3, gg = o & 7, kb = c >> 3, tt = c & 3, j = (c >> 2) & 1;
        uint32_t* cell = sB + (((n * KS + kb) * 8 + gg) << 4) + (tt << 2);
        cell[j] = hi;
        cell[2 + j] = lo;
    }

    // ---- stage A (fused affine+relu; optional raw input stats) ----
    int c0 = (tid * 4) % CIN;          // fixed per thread (1024 % CIN == 0)
    float4 sc4, sh4;
    if (AFF) { sc4 = *(const float4*)&scale[c0]; sh4 = *(const float4*)&shift[c0]; }
    float4 ls = make_float4(0.f, 0.f, 0.f, 0.f);
    float4 lq = make_float4(0.f, 0.f, 0.f, 0.f);
    for (int i = tid * 4; i < M * CIN; i += 1024) {
        int r = i / CIN, c = i % CIN;
        float4 v = make_float4(0.f, 0.f, 0.f, 0.f);
        if (row0 + r < nrows) v = *(const float4*)&X[(size_t)(row0 + r) * CIN + c];
        if (INSTATS) {
            ls.x += v.x; ls.y += v.y; ls.z += v.z; ls.w += v.w;
            lq.x += v.x * v.x; lq.y += v.y * v.y; lq.z += v.z * v.z; lq.w += v.w * v.w;
        }
        if (AFF) {
            v.x = fmaxf(fmaf(v.x, sc4.x, sh4.x), 0.f);
            v.y = fmaxf(fmaf(v.y, sc4.y, sh4.y), 0.f);
            v.z = fmaxf(fmaf(v.z, sc4.z, sh4.z), 0.f);
            v.w = fmaxf(fmaf(v.w, sc4.w, sh4.w), 0.f);
        }
        *(float4*)&sA[r * LDA + c] = v;
    }
    if (INSTATS) {
        atomicAdd(&sS[c0 + 0], ls.x); atomicAdd(&sS[c0 + 1], ls.y);
        atomicAdd(&sS[c0 + 2], ls.z); atomicAdd(&sS[c0 + 3], ls.w);
        atomicAdd(&sS[128 + c0 + 0], lq.x); atomicAdd(&sS[128 + c0 + 1], lq.y);
        atomicAdd(&sS[128 + c0 + 2], lq.z); atomicAdd(&sS[128 + c0 + 3], lq.w);
    }
    __syncthreads();
    if (INSTATS && tid < CIN) {
        atomicAdd(&accout[tid], (double)sS[tid]);
        atomicAdd(&accout[CIN + tid], (double)sS[128 + tid]);
    }

    // ---- mma compute: warp owns rows [16*wid, 16*wid+16) ----
    int ar = wid * 16 + g;
    float acc[NT][4];
#pragma unroll
    for (int n = 0; n < NT; n++)
#pragma unroll
        for (int j = 0; j < 4; j++) acc[n][j] = 0.f;

    const uint32_t* bBase = sB + (t << 2);
#pragma unroll
    for (int kb = 0; kb < KS; kb++) {
        int k0 = kb * 8;
        float af[4];
        af[0] = sA[ar * LDA + k0 + t];
        af[1] = sA[(ar + 8) * LDA + k0 + t];
        af[2] = sA[ar * LDA + k0 + t + 4];
        af[3] = sA[(ar + 8) * LDA + k0 + t + 4];
        uint32_t ah[4], al[4];
#pragma unroll
        for (int j = 0; j < 4; j++) {
            ah[j] = f2tf32(af[j]);
            al[j] = f2tf32(af[j] - __uint_as_float(ah[j]));
        }
#pragma unroll
        for (int n = 0; n < NT; n++) {
            uint4 b = *(const uint4*)(bBase + (((n * KS + kb) * 8 + g) << 4));
            mma8(acc[n], ah, b.x, b.y);   // ah * bh
            mma8(acc[n], ah, b.z, b.w);   // ah * bl
            mma8(acc[n], al, b.x, b.y);   // al * bh
        }
    }

    // ---- store (fragment layout: c0/c1 at (row, 2t), c2/c3 at (row+8, 2t)) ----
    int r0 = row0 + wid * 16 + g;
    bool v0 = r0 < nrows, v1 = (r0 + 8) < nrows;
#pragma unroll
    for (int n = 0; n < NT; n++) {
        int col = n * 8 + 2 * t;
        if (col < NOUT) {
            if (v0) *(float2*)&Y[(size_t)r0 * NOUT + col]       = make_float2(acc[n][0], acc[n][1]);
            if (v1) *(float2*)&Y[(size_t)(r0 + 8) * NOUT + col] = make_float2(acc[n][2], acc[n][3]);
        }
    }

    // ---- fused output-channel stats via shfl reduce over fragment rows ----
    if (OUTSTATS) {
#pragma unroll
        for (int n = 0; n < NT; n++) {
            float e0 = v0 ? acc[n][0] : 0.f, o0 = v0 ? acc[n][1] : 0.f;
            float e1 = v1 ? acc[n][2] : 0.f, o1 = v1 ? acc[n][3] : 0.f;
            float se = e0 + e1, qe = e0 * e0 + e1 * e1;
            float so = o0 + o1, qo = o0 * o0 + o1 * o1;
#pragma unroll
            for (int off = 4; off < 32; off <<= 1) {
                se += __shfl_xor_sync(0xffffffffu, se, off);
                qe += __shfl_xor_sync(0xffffffffu, qe, off);
                so += __shfl_xor_sync(0xffffffffu, so, off);
                qo += __shfl_xor_sync(0xffffffffu, qo, off);
            }
            if (g == 0) {
                int col = n * 8 + 2 * t;
                atomicAdd(&sS[col], se);       atomicAdd(&sS[col + 1], so);
                atomicAdd(&sS[128 + col], qe); atomicAdd(&sS[128 + col + 1], qo);
            }
        }
        __syncthreads();
        if (tid < NOUT) {
            atomicAdd(&accout[tid], (double)sS[tid]);
            atomicAdd(&accout[NOUT + tid], (double)sS[128 + tid]);
        }
    }
}

// ---------------- per-position epilogue ----------------
__global__ void final_kernel(const int* __restrict__ idx, const float* __restrict__ bary,
                             const float* __restrict__ x3, const float* __restrict__ proj,
                             const float* __restrict__ gamma, const float* __restrict__ beta,
                             const float* __restrict__ dWw, const float* __restrict__ dWb,
                             const float* __restrict__ clsb, float* __restrict__ out, int npos) {
    int p = blockIdx.x * blockDim.x + threadIdx.x;
    if (p >= npos) return;

    int4   vi = ((const int4*)idx)[p];
    float4 vb = ((const float4*)bary)[p];
    int   ivs[4] = {vi.x, vi.y, vi.z, vi.w};
    float bb[4]  = {vb.x, vb.y, vb.z, vb.w};

    float row[4][9];
#pragma unroll
    for (int v = 0; v < 4; v++) {
        const float4* xp = (const float4*)(x3 + (size_t)ivs[v] * 8);
        float4 a = __ldg(xp);
        float4 b = __ldg(xp + 1);
        row[v][0] = a.x; row[v][1] = a.y; row[v][2] = a.z; row[v][3] = a.w;
        row[v][4] = b.x; row[v][5] = b.y; row[v][6] = b.z; row[v][7] = b.w;
        row[v][8] = bb[v];
    }

    float wv[4];
    float db = __ldg(dWb);
#pragma unroll
    for (int v = 0; v < 4; v++) wv[v] = db;

#pragma unroll
    for (int j = 0; j < 9; j++) {
        float m   = fmaxf(fmaxf(row[0][j], row[1][j]), fmaxf(row[2][j], row[3][j]));
        float off = fmaf(__ldg(&gamma[j]), m, __ldg(&beta[j]));
        float dw  = __ldg(&dWw[j]);
#pragma unroll
        for (int v = 0; v < 4; v++) wv[v] = fmaf(row[v][j] - off, dw, wv[v]);
    }
#pragma unroll
    for (int v = 0; v < 4; v++) wv[v] += bb[v];

    float o[20];
#pragma unroll
    for (int c = 0; c < 20; c++) o[c] = __ldg(&clsb[c]);

#pragma unroll
    for (int v = 0; v < 4; v++) {
        const float4* pr = (const float4*)(proj + (size_t)ivs[v] * 20);
        float w = wv[v];
#pragma unroll
        for (int k = 0; k < 5; k++) {
            float4 q = __ldg(pr + k);
            o[4 * k + 0] = fmaf(w, q.x, o[4 * k + 0]);
            o[4 * k + 1] = fmaf(w, q.y, o[4 * k + 1]);
            o[4 * k + 2] = fmaf(w, q.z, o[4 * k + 2]);
            o[4 * k + 3] = fmaf(w, q.w, o[4 * k + 3]);
        }
    }

    float4* op = (float4*)(out + (size_t)p * 20);
#pragma unroll
    for (int k = 0; k < 5; k++)
        op[k] = make_float4(o[4 * k], o[4 * k + 1], o[4 * k + 2], o[4 * k + 3]);
}

// ---------------- launch ----------------
extern "C" void kernel_launch(void* const* d_in, const int* in_sizes, int n_in,
                              void* d_out, int out_size) {
    const float* lv    = (const float*)d_in[0];
    const int*   idx   = (const int*)d_in[2];
    const float* bary  = (const float*)d_in[3];
    const float* gn0_w = (const float*)d_in[4];
    const float* gn0_b = (const float*)d_in[5];
    const float* W0    = (const float*)d_in[6];
    const float* gn1_w = (const float*)d_in[7];
    const float* gn1_b = (const float*)d_in[8];
    const float* W1    = (const float*)d_in[9];
    const float* gn2_w = (const float*)d_in[10];
    const float* gn2_b = (const float*)d_in[11];
    const float* W2    = (const float*)d_in[12];
    const float* gamma = (const float*)d_in[13];
    const float* beta  = (const float*)d_in[14];
    const float* dW_W  = (const float*)d_in[15];
    const float* dW_b  = (const float*)d_in[16];
    const float* clsW  = (const float*)d_in[17];
    const float* clsb  = (const float*)d_in[18];
    float* out = (float*)d_out;

    float*  x1;   cudaGetSymbolAddress((void**)&x1,   g_x1);
    float*  x2;   cudaGetSymbolAddress((void**)&x2,   g_x2);
    float*  x3;   cudaGetSymbolAddress((void**)&x3,   g_x3);
    float*  proj; cudaGetSymbolAddress((void**)&proj, g_proj);
    double* acc;  cudaGetSymbolAddress((void**)&acc,  g_acc);
    float*  scl;  cudaGetSymbolAddress((void**)&scl,  g_scale);
    float*  shf;  cudaGetSymbolAddress((void**)&shf,  g_shift);

    // dynamic smem bytes: M*LDA*4 + NPAD*CIN*8 + 1024
    const int smP  = 128 * 68 * 4 + 24 * 64 * 8 + 1024;   // 48128
    const int smL0 = 128 * 68 * 4 + 64 * 64 * 8 + 1024;   // 68608
    const int smL1 = 128 * 68 * 4 + 32 * 64 * 8 + 1024;   // 52224
    const int smL2 = 128 * 36 * 4 +  8 * 32 * 8 + 1024;   // 21504

    cudaFuncSetAttribute((const void*)mgemm_kernel<64, 20, 24, false, true,  false>,
                         cudaFuncAttributeMaxDynamicSharedMemorySize, smP);
    cudaFuncSetAttribute((const void*)mgemm_kernel<64, 64, 64, true,  false, true >,
                         cudaFuncAttributeMaxDynamicSharedMemorySize, smL0);
    cudaFuncSetAttribute((const void*)mgemm_kernel<64, 32, 32, true,  false, true >,
                         cudaFuncAttributeMaxDynamicSharedMemorySize, smL1);
    cudaFuncSetAttribute((const void*)mgemm_kernel<32, 8,  8,  true,  false, false>,
                         cudaFuncAttributeMaxDynamicSharedMemorySize, smL2);

    const int gt = (NVERT + 127) / 128;   // 2344

    init_acc_kernel<<<1, 320>>>();

    // proj = lv @ cls_W^T  (+ fused lv stats for GN0)
    mgemm_kernel<64, 20, 24, false, true, false><<<gt, 256, smP>>>(
        lv, clsW, nullptr, nullptr, proj, acc, NVERT);
    finalize_kernel<64><<<1, 64>>>(acc, gn0_w, gn0_b, scl, shf, NVERT);

    // layer0: GN0+ReLU fused, 64->64 (+x1 stats)
    mgemm_kernel<64, 64, 64, true, false, true><<<gt, 256, smL0>>>(
        lv, W0, scl, shf, x1, acc + 128, NVERT);
    finalize_kernel<64><<<1, 64>>>(acc + 128, gn1_w, gn1_b, scl + 64, shf + 64, NVERT);

    // layer1: GN1+ReLU fused, 64->32 (+x2 stats)
    mgemm_kernel<64, 32, 32, true, false, true><<<gt, 256, smL1>>>(
        x1, W1, scl + 64, shf + 64, x2, acc + 256, NVERT);
    finalize_kernel<32><<<1, 32>>>(acc + 256, gn2_w, gn2_b, scl + 128, shf + 128, NVERT);

    // layer2: GN2+ReLU fused, 32->8
    mgemm_kernel<32, 8, 8, true, false, false><<<gt, 256, smL2>>>(
        x2, W2, scl + 128, shf + 128, x3, nullptr, NVERT);

    // per-position gather + simplex norm + delta weights + classify
    final_kernel<<<(NPOS + 255) / 256, 256>>>(idx, bary, x3, proj, gamma, beta,
                                              dW_W, dW_b, clsb, out, NPOS);
}

// round 12
// speedup vs baseline: 1.1947x; 1.1947x over previous
#include <cuda_runtime.h>
#include <math.h>
#include <stdint.h>

#define NVERT 300000
#define NPOS  500000

// ---------------- device scratch (no allocs allowed) ----------------
__device__ float  g_x1[NVERT * 64];
__device__ float  g_x2[NVERT * 32];
__device__ float  g_x3[NVERT * 8];
__device__ float  g_proj[NVERT * 20];
__device__ double g_acc[320];          // lv @0, x1 @128, x2 @256 (sum|sumsq)
__device__ float  g_scale[160];
__device__ float  g_shift[160];

__global__ void init_acc_kernel() {
    int i = threadIdx.x;
    if (i < 320) g_acc[i] = 0.0;
}

// ---------------- stats -> per-channel affine (GN folded) ----------------
template <int C>
__global__ void finalize_kernel(const double* __restrict__ acc,
                                const float* __restrict__ w, const float* __restrict__ b,
                                float* __restrict__ scale, float* __restrict__ shift, int nrows) {
    int c = threadIdx.x;
    if (c >= C) return;
    constexpr int CPG = C / 32;
    int g = c / CPG;
    double s = 0.0, q = 0.0;
#pragma unroll
    for (int j = 0; j < CPG; j++) {
        s += acc[g * CPG + j];
        q += acc[C + g * CPG + j];
    }
    double n   = (double)nrows * (double)CPG;
    double mu  = s / n;
    double var = q / n - mu * mu;
    float  rs  = (float)(1.0 / sqrt(var + 1e-5));
    float  sc  = w[c] * rs;
    scale[c] = sc;
    shift[c] = b[c] - (float)mu * sc;
}

// ---------------- tf32 mma helpers (legacy mma.sync, sm_80+ PTX) ----------------
__device__ __forceinline__ uint32_t f2tf32(float x) {
    uint32_t r;
    asm("cvt.rna.tf32.f32 %0, %1;" : "=r"(r) : "f"(x));
    return r;
}
__device__ __forceinline__ void mma8(float* c, const uint32_t* a, uint32_t b0, uint32_t b1) {
    asm volatile("mma.sync.aligned.m16n8k8.row.col.f32.tf32.tf32.f32 "
                 "{%0,%1,%2,%3}, {%4,%5,%6,%7}, {%8,%9}, {%0,%1,%2,%3};"
                 : "+f"(c[0]), "+f"(c[1]), "+f"(c[2]), "+f"(c[3])
                 : "r"(a[0]), "r"(a[1]), "r"(a[2]), "r"(a[3]), "r"(b0), "r"(b1));
}

// =====================================================================
// tf32 tensor-core GEMM: Y[r,o] = sum_k f(X[r,k]) * W[o,k], M=128/CTA.
// f = relu(x*scale+shift) if AFF.
// TERMS=3: D = ah*bh + ah*bl + al*bh  (fp32-accurate split)
// TERMS=2: D = ah*bh + al*bh = a*bh   (exact A, tf32 B; err ~1e-4)
// INSTATS: channel stats of raw X fused into staging.
// OUTSTATS: channel stats of Y fused via fragment shfl-reduce.
// =====================================================================
template <int CIN, int NOUT, int NPAD, bool AFF, bool INSTATS, bool OUTSTATS, int TERMS>
__global__ void __launch_bounds__(256)
mgemm_kernel(const float* __restrict__ X, const float* __restrict__ W,
             const float* __restrict__ scale, const float* __restrict__ shift,
             float* __restrict__ Y, double* __restrict__ accout, int nrows) {
    constexpr int M = 128, LDA = CIN + 4, NT = NPAD / 8;
    extern __shared__ float sm[];
    float* sA = sm;                    // [M][LDA]
    float* sW = sA + M * LDA;          // [NPAD][LDA]
    float* sS = sW + NPAD * LDA;       // [256]

    int tid = threadIdx.x, lane = tid & 31, wid = tid >> 5;
    int g = lane >> 2, t = lane & 3;
    int row0 = blockIdx.x * M;

    if (INSTATS || OUTSTATS) sS[tid] = 0.f;

    // ---- stage W (zero-pad rows >= NOUT) ----
    for (int i = tid * 4; i < NPAD * CIN; i += 1024) {
        int o = i / CIN, c = i % CIN;
        float4 w = make_float4(0.f, 0.f, 0.f, 0.f);
        if (o < NOUT) w = *(const float4*)&W[o * CIN + c];
        *(float4*)&sW[o * LDA + c] = w;
    }

    // ---- stage A (fused affine+relu; optional raw input stats) ----
    int c0 = (tid * 4) % CIN;          // fixed per thread (1024 % CIN == 0)
    float4 sc4, sh4;
    if (AFF) { sc4 = *(const float4*)&scale[c0]; sh4 = *(const float4*)&shift[c0]; }
    float4 ls = make_float4(0.f, 0.f, 0.f, 0.f);
    float4 lq = make_float4(0.f, 0.f, 0.f, 0.f);
    for (int i = tid * 4; i < M * CIN; i += 1024) {
        int r = i / CIN, c = i % CIN;
        float4 v = make_float4(0.f, 0.f, 0.f, 0.f);
        if (row0 + r < nrows) v = *(const float4*)&X[(size_t)(row0 + r) * CIN + c];
        if (INSTATS) {
            ls.x += v.x; ls.y += v.y; ls.z += v.z; ls.w += v.w;
            lq.x += v.x * v.x; lq.y += v.y * v.y; lq.z += v.z * v.z; lq.w += v.w * v.w;
        }
        if (AFF) {
            v.x = fmaxf(fmaf(v.x, sc4.x, sh4.x), 0.f);
            v.y = fmaxf(fmaf(v.y, sc4.y, sh4.y), 0.f);
            v.z = fmaxf(fmaf(v.z, sc4.z, sh4.z), 0.f);
            v.w = fmaxf(fmaf(v.w, sc4.w, sh4.w), 0.f);
        }
        *(float4*)&sA[r * LDA + c] = v;
    }
    if (INSTATS) {
        atomicAdd(&sS[c0 + 0], ls.x); atomicAdd(&sS[c0 + 1], ls.y);
        atomicAdd(&sS[c0 + 2], ls.z); atomicAdd(&sS[c0 + 3], ls.w);
        atomicAdd(&sS[128 + c0 + 0], lq.x); atomicAdd(&sS[128 + c0 + 1], lq.y);
        atomicAdd(&sS[128 + c0 + 2], lq.z); atomicAdd(&sS[128 + c0 + 3], lq.w);
    }
    __syncthreads();
    if (INSTATS && tid < CIN) {
        atomicAdd(&accout[tid], (double)sS[tid]);
        atomicAdd(&accout[CIN + tid], (double)sS[128 + tid]);
    }

    // ---- mma compute: warp owns rows [16*wid, 16*wid+16) ----
    int ar = wid * 16 + g;
    float acc[NT][4];
#pragma unroll
    for (int n = 0; n < NT; n++)
#pragma unroll
        for (int j = 0; j < 4; j++) acc[n][j] = 0.f;

#pragma unroll
    for (int k0 = 0; k0 < CIN; k0 += 8) {
        float af[4];
        af[0] = sA[ar * LDA + k0 + t];
        af[1] = sA[(ar + 8) * LDA + k0 + t];
        af[2] = sA[ar * LDA + k0 + t + 4];
        af[3] = sA[(ar + 8) * LDA + k0 + t + 4];
        uint32_t ah[4], al[4];
#pragma unroll
        for (int j = 0; j < 4; j++) {
            ah[j] = f2tf32(af[j]);
            al[j] = f2tf32(af[j] - __uint_as_float(ah[j]));
        }
#pragma unroll
        for (int n = 0; n < NT; n++) {
            float bf0 = sW[(n * 8 + g) * LDA + k0 + t];
            float bf1 = sW[(n * 8 + g) * LDA + k0 + t + 4];
            uint32_t bh0 = f2tf32(bf0), bh1 = f2tf32(bf1);
            mma8(acc[n], ah, bh0, bh1);               // ah * bh
            if (TERMS == 3) {
                uint32_t bl0 = f2tf32(bf0 - __uint_as_float(bh0));
                uint32_t bl1 = f2tf32(bf1 - __uint_as_float(bh1));
                mma8(acc[n], ah, bl0, bl1);           // ah * bl
            }
            mma8(acc[n], al, bh0, bh1);               // al * bh
        }
    }

    // ---- store (fragment layout: c0/c1 at (row, 2t), c2/c3 at (row+8, 2t)) ----
    int r0 = row0 + wid * 16 + g;
    bool v0 = r0 < nrows, v1 = (r0 + 8) < nrows;
#pragma unroll
    for (int n = 0; n < NT; n++) {
        int col = n * 8 + 2 * t;
        if (col < NOUT) {
            if (v0) *(float2*)&Y[(size_t)r0 * NOUT + col]       = make_float2(acc[n][0], acc[n][1]);
            if (v1) *(float2*)&Y[(size_t)(r0 + 8) * NOUT + col] = make_float2(acc[n][2], acc[n][3]);
        }
    }

    // ---- fused output-channel stats via shfl reduce over fragment rows ----
    if (OUTSTATS) {
#pragma unroll
        for (int n = 0; n < NT; n++) {
            float e0 = v0 ? acc[n][0] : 0.f, o0 = v0 ? acc[n][1] : 0.f;
            float e1 = v1 ? acc[n][2] : 0.f, o1 = v1 ? acc[n][3] : 0.f;
            float se = e0 + e1, qe = e0 * e0 + e1 * e1;
            float so = o0 + o1, qo = o0 * o0 + o1 * o1;
#pragma unroll
            for (int off = 4; off < 32; off <<= 1) {
                se += __shfl_xor_sync(0xffffffffu, se, off);
                qe += __shfl_xor_sync(0xffffffffu, qe, off);
                so += __shfl_xor_sync(0xffffffffu, so, off);
                qo += __shfl_xor_sync(0xffffffffu, qo, off);
            }
            if (g == 0) {
                int col = n * 8 + 2 * t;
                atomicAdd(&sS[col], se);       atomicAdd(&sS[col + 1], so);
                atomicAdd(&sS[128 + col], qe); atomicAdd(&sS[128 + col + 1], qo);
            }
        }
        __syncthreads();
        if (tid < NOUT) {
            atomicAdd(&accout[tid], (double)sS[tid]);
            atomicAdd(&accout[NOUT + tid], (double)sS[128 + tid]);
        }
    }
}

// ---------------- per-position epilogue ----------------
__global__ void final_kernel(const int* __restrict__ idx, const float* __restrict__ bary,
                             const float* __restrict__ x3, const float* __restrict__ proj,
                             const float* __restrict__ gamma, const float* __restrict__ beta,
                             const float* __restrict__ dWw, const float* __restrict__ dWb,
                             const float* __restrict__ clsb, float* __restrict__ out, int npos) {
    int p = blockIdx.x * blockDim.x + threadIdx.x;
    if (p >= npos) return;

    int4   vi = ((const int4*)idx)[p];
    float4 vb = ((const float4*)bary)[p];
    int   ivs[4] = {vi.x, vi.y, vi.z, vi.w};
    float bb[4]  = {vb.x, vb.y, vb.z, vb.w};

    float row[4][9];
#pragma unroll
    for (int v = 0; v < 4; v++) {
        const float4* xp = (const float4*)(x3 + (size_t)ivs[v] * 8);
        float4 a = __ldg(xp);
        float4 b = __ldg(xp + 1);
        row[v][0] = a.x; row[v][1] = a.y; row[v][2] = a.z; row[v][3] = a.w;
        row[v][4] = b.x; row[v][5] = b.y; row[v][6] = b.z; row[v][7] = b.w;
        row[v][8] = bb[v];
    }

    float wv[4];
    float db = __ldg(dWb);
#pragma unroll
    for (int v = 0; v < 4; v++) wv[v] = db;

#pragma unroll
    for (int j = 0; j < 9; j++) {
        float m   = fmaxf(fmaxf(row[0][j], row[1][j]), fmaxf(row[2][j], row[3][j]));
        float off = fmaf(__ldg(&gamma[j]), m, __ldg(&beta[j]));
        float dw  = __ldg(&dWw[j]);
#pragma unroll
        for (int v = 0; v < 4; v++) wv[v] = fmaf(row[v][j] - off, dw, wv[v]);
    }
#pragma unroll
    for (int v = 0; v < 4; v++) wv[v] += bb[v];

    float o[20];
#pragma unroll
    for (int c = 0; c < 20; c++) o[c] = __ldg(&clsb[c]);

#pragma unroll
    for (int v = 0; v < 4; v++) {
        const float4* pr = (const float4*)(proj + (size_t)ivs[v] * 20);
        float w = wv[v];
#pragma unroll
        for (int k = 0; k < 5; k++) {
            float4 q = __ldg(pr + k);
            o[4 * k + 0] = fmaf(w, q.x, o[4 * k + 0]);
            o[4 * k + 1] = fmaf(w, q.y, o[4 * k + 1]);
            o[4 * k + 2] = fmaf(w, q.z, o[4 * k + 2]);
            o[4 * k + 3] = fmaf(w, q.w, o[4 * k + 3]);
        }
    }

    float4* op = (float4*)(out + (size_t)p * 20);
#pragma unroll
    for (int k = 0; k < 5; k++)
        op[k] = make_float4(o[4 * k], o[4 * k + 1], o[4 * k + 2], o[4 * k + 3]);
}

// ---------------- launch ----------------
extern "C" void kernel_launch(void* const* d_in, const int* in_sizes, int n_in,
                              void* d_out, int out_size) {
    const float* lv    = (const float*)d_in[0];
    const int*   idx   = (const int*)d_in[2];
    const float* bary  = (const float*)d_in[3];
    const float* gn0_w = (const float*)d_in[4];
    const float* gn0_b = (const float*)d_in[5];
    const float* W0    = (const float*)d_in[6];
    const float* gn1_w = (const float*)d_in[7];
    const float* gn1_b = (const float*)d_in[8];
    const float* W1    = (const float*)d_in[9];
    const float* gn2_w = (const float*)d_in[10];
    const float* gn2_b = (const float*)d_in[11];
    const float* W2    = (const float*)d_in[12];
    const float* gamma = (const float*)d_in[13];
    const float* beta  = (const float*)d_in[14];
    const float* dW_W  = (const float*)d_in[15];
    const float* dW_b  = (const float*)d_in[16];
    const float* clsW  = (const float*)d_in[17];
    const float* clsb  = (const float*)d_in[18];
    float* out = (float*)d_out;

    float*  x1;   cudaGetSymbolAddress((void**)&x1,   g_x1);
    float*  x2;   cudaGetSymbolAddress((void**)&x2,   g_x2);
    float*  x3;   cudaGetSymbolAddress((void**)&x3,   g_x3);
    float*  proj; cudaGetSymbolAddress((void**)&proj, g_proj);
    double* acc;  cudaGetSymbolAddress((void**)&acc,  g_acc);
    float*  scl;  cudaGetSymbolAddress((void**)&scl,  g_scale);
    float*  shf;  cudaGetSymbolAddress((void**)&shf,  g_shift);

    // dynamic smem bytes: (128*LDA + NPAD*LDA + 256) * 4   (R8 sizes: 4 CTAs/SM)
    const int smP  = (128 * 68 + 24 * 68 + 256) * 4;   // 42368
    const int smL0 = (128 * 68 + 64 * 68 + 256) * 4;   // 53248
    const int smL1 = (128 * 68 + 32 * 68 + 256) * 4;   // 44544
    const int smL2 = (128 * 36 +  8 * 36 + 256) * 4;   // 20608

    cudaFuncSetAttribute((const void*)mgemm_kernel<64, 20, 24, false, true,  false, 3>,
                         cudaFuncAttributeMaxDynamicSharedMemorySize, smP);
    cudaFuncSetAttribute((const void*)mgemm_kernel<64, 64, 64, true,  false, true,  2>,
                         cudaFuncAttributeMaxDynamicSharedMemorySize, smL0);
    cudaFuncSetAttribute((const void*)mgemm_kernel<64, 32, 32, true,  false, true,  2>,
                         cudaFuncAttributeMaxDynamicSharedMemorySize, smL1);
    cudaFuncSetAttribute((const void*)mgemm_kernel<32, 8,  8,  true,  false, false, 3>,
                         cudaFuncAttributeMaxDynamicSharedMemorySize, smL2);

    const int gt = (NVERT + 127) / 128;   // 2344

    init_acc_kernel<<<1, 320>>>();

    // proj = lv @ cls_W^T  (3-term; + fused lv stats for GN0)
    mgemm_kernel<64, 20, 24, false, true, false, 3><<<gt, 256, smP>>>(
        lv, clsW, nullptr, nullptr, proj, acc, NVERT);
    finalize_kernel<64><<<1, 64>>>(acc, gn0_w, gn0_b, scl, shf, NVERT);

    // layer0: GN0+ReLU fused, 64->64, 2-term (+x1 stats)
    mgemm_kernel<64, 64, 64, true, false, true, 2><<<gt, 256, smL0>>>(
        lv, W0, scl, shf, x1, acc + 128, NVERT);
    finalize_kernel<64><<<1, 64>>>(acc + 128, gn1_w, gn1_b, scl + 64, shf + 64, NVERT);

    // layer1: GN1+ReLU fused, 64->32, 2-term (+x2 stats)
    mgemm_kernel<64, 32, 32, true, false, true, 2><<<gt, 256, smL1>>>(
        x1, W1, scl + 64, shf + 64, x2, acc + 256, NVERT);
    finalize_kernel<32><<<1, 32>>>(acc + 256, gn2_w, gn2_b, scl + 128, shf + 128, NVERT);

    // layer2: GN2+ReLU fused, 32->8, 3-term
    mgemm_kernel<32, 8, 8, true, false, false, 3><<<gt, 256, smL2>>>(
        x2, W2, scl + 128, shf + 128, x3, nullptr, NVERT);

    // per-position gather + simplex norm + delta weights + classify
    final_kernel<<<(NPOS + 255) / 256, 256>>>(idx, bary, x3, proj, gamma, beta,
                                              dW_W, dW_b, clsb, out, NPOS);
}